// round 1
// baseline (speedup 1.0000x reference)
#include <cuda_runtime.h>

#define R     5
#define TILE  32
#define HT    42          // TILE + 2*R
#define HBS   36          // padded col stride for h-blur smem (16B-aligned float4 rows)
#define NIMG  48          // 16 batch * 3 channels, depthwise => independent planes

// Normalized 11-tap Gaussian (sigma=1.5), matches jnp within ~1e-7
__constant__ float GW[11] = {
    0.00102838f, 0.00759876f, 0.03600075f, 0.10936071f, 0.21300558f,
    0.26601173f,
    0.21300558f, 0.10936071f, 0.03600075f, 0.00759876f, 0.00102838f
};

// Scratch pyramids (ping-pong): A holds levels 1 (256^2) and 3 (64^2),
// B holds levels 2 (128^2) and 4 (32^2).
__device__ float  g_bufAx[NIMG * 256 * 256];
__device__ float  g_bufAy[NIMG * 256 * 256];
__device__ float  g_bufBx[NIMG * 128 * 128];
__device__ float  g_bufBy[NIMG * 128 * 128];
__device__ double g_acc[5];

__global__ void zero_acc_kernel() {
    if (threadIdx.x < 5) g_acc[threadIdx.x] = 0.0;
}

// Fused per-level SSIM: loads x,y tile(+halo), separable Gaussian blur of
// {x, y, x^2, y^2, xy}, per-pixel SSIM, block reduction into g_acc[level].
__global__ __launch_bounds__(256) void ssim_level_kernel(
    const float* __restrict__ X, const float* __restrict__ Y,
    int H, int W, double* __restrict__ acc)
{
    __shared__ float sx[HT][HT + 2];
    __shared__ float sy[HT][HT + 2];
    __shared__ float hb[5][HT][HBS];
    __shared__ float wsum[8];

    const int tid  = threadIdx.x;
    const int img  = blockIdx.z;
    const int base = img * H * W;
    const int r0   = blockIdx.y * TILE - R;
    const int c0   = blockIdx.x * TILE - R;

    // ---- load tile + halo (zero padding to match conv padding) ----
    for (int i = tid; i < HT * HT; i += 256) {
        int r  = i / HT, c = i - r * HT;
        int gr = r0 + r, gc = c0 + c;
        float xv = 0.0f, yv = 0.0f;
        if (gr >= 0 && gr < H && gc >= 0 && gc < W) {
            int gi = base + gr * W + gc;
            xv = X[gi];
            yv = Y[gi];
        }
        sx[r][c] = xv;
        sy[r][c] = yv;
    }
    __syncthreads();

    // ---- horizontal blur of 5 fields (products formed inline) ----
    for (int i = tid; i < HT * TILE; i += 256) {
        int r = i >> 5, c = i & 31;
        float s1 = 0.f, s2 = 0.f, s3 = 0.f, s4 = 0.f, s5 = 0.f;
#pragma unroll
        for (int t = 0; t < 11; t++) {
            float w  = GW[t];
            float xv = sx[r][c + t];
            float yv = sy[r][c + t];
            float wx = w * xv;
            float wy = w * yv;
            s1 += wx;
            s2 += wy;
            s3 += wx * xv;
            s4 += wy * yv;
            s5 += wx * yv;
        }
        hb[0][r][c] = s1;
        hb[1][r][c] = s2;
        hb[2][r][c] = s3;
        hb[3][r][c] = s4;
        hb[4][r][c] = s5;
    }
    __syncthreads();

    // ---- vertical blur + SSIM, 4 pixels/thread via float4 LDS ----
    const int vr = tid >> 3;          // output row   0..31
    const int vc = (tid & 7) * 4;     // output col group (float4 aligned)

    float4 m1  = {0.f, 0.f, 0.f, 0.f};
    float4 m2  = {0.f, 0.f, 0.f, 0.f};
    float4 e11 = {0.f, 0.f, 0.f, 0.f};
    float4 e22 = {0.f, 0.f, 0.f, 0.f};
    float4 e12 = {0.f, 0.f, 0.f, 0.f};
#pragma unroll
    for (int t = 0; t < 11; t++) {
        float  w = GW[t];
        float4 a;
        a = *(const float4*)&hb[0][vr + t][vc];
        m1.x += w * a.x; m1.y += w * a.y; m1.z += w * a.z; m1.w += w * a.w;
        a = *(const float4*)&hb[1][vr + t][vc];
        m2.x += w * a.x; m2.y += w * a.y; m2.z += w * a.z; m2.w += w * a.w;
        a = *(const float4*)&hb[2][vr + t][vc];
        e11.x += w * a.x; e11.y += w * a.y; e11.z += w * a.z; e11.w += w * a.w;
        a = *(const float4*)&hb[3][vr + t][vc];
        e22.x += w * a.x; e22.y += w * a.y; e22.z += w * a.z; e22.w += w * a.w;
        a = *(const float4*)&hb[4][vr + t][vc];
        e12.x += w * a.x; e12.y += w * a.y; e12.z += w * a.z; e12.w += w * a.w;
    }

    const float C1 = 4.0e-4f;   // (0.01*2)^2
    const float C2 = 3.6e-3f;   // (0.03*2)^2
    float lsum = 0.f;
#pragma unroll
    for (int k = 0; k < 4; k++) {
        float mu1 = (&m1.x)[k],  mu2 = (&m2.x)[k];
        float x2  = (&e11.x)[k], y2  = (&e22.x)[k], xy = (&e12.x)[k];
        float mu1sq = mu1 * mu1;
        float mu2sq = mu2 * mu2;
        float mu12  = mu1 * mu2;
        float s1c   = x2 - mu1sq;
        float s2c   = y2 - mu2sq;
        float s12   = xy - mu12;
        float num   = (2.f * mu12 + C1) * (2.f * s12 + C2);
        float den   = (mu1sq + mu2sq + C1) * (s1c + s2c + C2);
        lsum += __fdividef(num, den + 1e-8f);
    }

    // ---- block reduction -> one double atomic per block ----
#pragma unroll
    for (int o = 16; o > 0; o >>= 1)
        lsum += __shfl_xor_sync(0xFFFFFFFFu, lsum, o);
    if ((tid & 31) == 0) wsum[tid >> 5] = lsum;
    __syncthreads();
    if (tid == 0) {
        float b = 0.f;
#pragma unroll
        for (int i = 0; i < 8; i++) b += wsum[i];
        atomicAdd(acc, (double)b);
    }
}

// 2x2 average pool (VALID), processes both x and y planes.
__global__ __launch_bounds__(256) void down2_kernel(
    const float* __restrict__ xin, const float* __restrict__ yin,
    float* __restrict__ xout, float* __restrict__ yout, int Ho, int Wo)
{
    int idx   = blockIdx.x * 256 + threadIdx.x;
    int total = NIMG * Ho * Wo;
    if (idx >= total) return;
    int Wi  = Wo * 2;
    int img = idx / (Ho * Wo);
    int rem = idx - img * (Ho * Wo);
    int r   = rem / Wo;
    int c   = rem - r * Wo;
    int ib  = img * (Ho * 2) * Wi + (2 * r) * Wi + 2 * c;

    float2 a = *(const float2*)(xin + ib);
    float2 b = *(const float2*)(xin + ib + Wi);
    xout[idx] = 0.25f * (a.x + a.y + b.x + b.y);

    float2 cy = *(const float2*)(yin + ib);
    float2 dy = *(const float2*)(yin + ib + Wi);
    yout[idx] = 0.25f * (cy.x + cy.y + dy.x + dy.y);
}

__global__ void finish_kernel(float* __restrict__ out) {
    const double w[5] = {0.0448, 0.2856, 0.3001, 0.2363, 0.1333};
    const double wsumv = 1.0001;  // sum of weights (reference normalizes)
    double cnt = (double)NIMG * 512.0 * 512.0;
    double m = 0.0;
#pragma unroll
    for (int l = 0; l < 5; l++) {
        m += (w[l] / wsumv) * (g_acc[l] / cnt);
        cnt *= 0.25;
    }
    out[0] = (float)(1.0 - m);
}

extern "C" void kernel_launch(void* const* d_in, const int* in_sizes, int n_in,
                              void* d_out, int out_size)
{
    (void)in_sizes; (void)n_in; (void)out_size;
    const float* pred   = (const float*)d_in[0];
    const float* target = (const float*)d_in[1];
    float* out = (float*)d_out;

    float *bAx, *bAy, *bBx, *bBy;
    double* acc;
    cudaGetSymbolAddress((void**)&bAx, g_bufAx);
    cudaGetSymbolAddress((void**)&bAy, g_bufAy);
    cudaGetSymbolAddress((void**)&bBx, g_bufBx);
    cudaGetSymbolAddress((void**)&bBy, g_bufBy);
    cudaGetSymbolAddress((void**)&acc, g_acc);

    zero_acc_kernel<<<1, 32>>>();

    // Level 0: 512x512
    ssim_level_kernel<<<dim3(16, 16, NIMG), 256>>>(pred, target, 512, 512, acc + 0);
    {
        int total = NIMG * 256 * 256;
        down2_kernel<<<(total + 255) / 256, 256>>>(pred, target, bAx, bAy, 256, 256);
    }
    // Level 1: 256x256
    ssim_level_kernel<<<dim3(8, 8, NIMG), 256>>>(bAx, bAy, 256, 256, acc + 1);
    {
        int total = NIMG * 128 * 128;
        down2_kernel<<<(total + 255) / 256, 256>>>(bAx, bAy, bBx, bBy, 128, 128);
    }
    // Level 2: 128x128
    ssim_level_kernel<<<dim3(4, 4, NIMG), 256>>>(bBx, bBy, 128, 128, acc + 2);
    {
        int total = NIMG * 64 * 64;
        down2_kernel<<<(total + 255) / 256, 256>>>(bBx, bBy, bAx, bAy, 64, 64);
    }
    // Level 3: 64x64
    ssim_level_kernel<<<dim3(2, 2, NIMG), 256>>>(bAx, bAy, 64, 64, acc + 3);
    {
        int total = NIMG * 32 * 32;
        down2_kernel<<<(total + 255) / 256, 256>>>(bAx, bAy, bBx, bBy, 32, 32);
    }
    // Level 4: 32x32
    ssim_level_kernel<<<dim3(1, 1, NIMG), 256>>>(bBx, bBy, 32, 32, acc + 4);

    finish_kernel<<<1, 1>>>(out);
}

// round 2
// speedup vs baseline: 1.4625x; 1.4625x over previous
#include <cuda_runtime.h>

#define R     5
#define TILE  32
#define HT    42          // TILE + 2*R
#define SXS   44          // padded stride for input tiles (rows 16B-aligned)
#define HBS   44          // padded stride for blurred fields (rows 16B-aligned)
#define NIMG  48          // 16 batch * 3 channels (depthwise -> independent planes)

// Normalized 11-tap Gaussian (sigma=1.5) as compile-time literals -> FFMA-imm
__device__ __forceinline__ float gw(int t) {
    constexpr float W[11] = {
        0.00102838f, 0.00759876f, 0.03600075f, 0.10936071f, 0.21300558f,
        0.26601173f,
        0.21300558f, 0.10936071f, 0.03600075f, 0.00759876f, 0.00102838f
    };
    return W[t];
}

// Scratch pyramids (ping-pong between A and B)
__device__ float  g_bufAx[NIMG * 256 * 256];
__device__ float  g_bufAy[NIMG * 256 * 256];
__device__ float  g_bufBx[NIMG * 128 * 128];
__device__ float  g_bufBy[NIMG * 128 * 128];
__device__ double g_acc[5];

__global__ void zero_acc_kernel() {
    if (threadIdx.x < 5) g_acc[threadIdx.x] = 0.0;
}

// Fused per-level SSIM + optional 2x2 avg-pool for the next level.
// Pass 1: VERTICAL blur (column-sliding, scalar conflict-free LDS) of
//         {x, y, x^2, y^2, xy} -> hb (5 fields, 32 rows x 42 cols).
// Pass 2: HORIZONTAL blur reading contiguous float4 rows, then SSIM + reduce.
template<bool POOL>
__global__ __launch_bounds__(256) void ssim_level_kernel(
    const float* __restrict__ X, const float* __restrict__ Y,
    int H, int W, double* __restrict__ acc,
    float* __restrict__ PX, float* __restrict__ PY)
{
    __shared__ float sx[HT][SXS];
    __shared__ float sy[HT][SXS];
    __shared__ float hb[5][TILE][HBS];
    __shared__ float wsum[8];

    const int tid  = threadIdx.x;
    const int img  = blockIdx.z;
    const int base = img * H * W;
    const int r0   = blockIdx.y * TILE - R;
    const int c0   = blockIdx.x * TILE - R;

    // ---- load tile + halo (zero padding outside image) ----
    for (int i = tid; i < HT * HT; i += 256) {
        int r  = i / HT, c = i - r * HT;
        int gr = r0 + r, gc = c0 + c;
        float xv = 0.0f, yv = 0.0f;
        if ((unsigned)gr < (unsigned)H && (unsigned)gc < (unsigned)W) {
            int gi = base + gr * W + gc;
            xv = X[gi];
            yv = Y[gi];
        }
        sx[r][c] = xv;
        sy[r][c] = yv;
    }
    __syncthreads();

    // ---- fused 2x2 avg-pool of the central 32x32 (input for next level) ----
    if (POOL) {
        int pr = tid >> 4, pc = tid & 15;
        int rr = R + 2 * pr, cc = R + 2 * pc;
        float px = 0.25f * (sx[rr][cc] + sx[rr][cc + 1] + sx[rr + 1][cc] + sx[rr + 1][cc + 1]);
        float py = 0.25f * (sy[rr][cc] + sy[rr][cc + 1] + sy[rr + 1][cc] + sy[rr + 1][cc + 1]);
        int Ho = H >> 1, Wo = W >> 1;
        int o  = img * Ho * Wo + (blockIdx.y * 16 + pr) * Wo + blockIdx.x * 16 + pc;
        PX[o] = px;
        PY[o] = py;
    }

    // ---- pass 1: vertical blur, 5 fields, 4 output rows per unit ----
    // unit u -> (c = u%42, row group = u/42); outputs rows 4*rg..4*rg+3 at col c
    for (int u = tid; u < HT * 8; u += 256) {
        int c  = u % HT;
        int rb = (u / HT) * 4;
        float av[5][4] = {};
#pragma unroll
        for (int t = 0; t < 14; t++) {
            float xv = sx[rb + t][c];
            float yv = sy[rb + t][c];
            float x2 = xv * xv, y2 = yv * yv, xy = xv * yv;
#pragma unroll
            for (int k = 0; k < 4; k++) {
                int tt = t - k;                 // compile-time after unroll
                if (tt >= 0 && tt <= 10) {
                    float w = gw(tt);
                    av[0][k] += w * xv;
                    av[1][k] += w * yv;
                    av[2][k] += w * x2;
                    av[3][k] += w * y2;
                    av[4][k] += w * xy;
                }
            }
        }
#pragma unroll
        for (int f = 0; f < 5; f++)
#pragma unroll
            for (int k = 0; k < 4; k++)
                hb[f][rb + k][c] = av[f][k];
    }
    __syncthreads();

    // ---- pass 2: horizontal blur (float4 row reads) + SSIM ----
    const int vr = tid >> 3;          // output row 0..31
    const int vc = (tid & 7) * 4;     // output col group (16B aligned)

    float m[5][4] = {};
#pragma unroll
    for (int f = 0; f < 5; f++) {
        float v[16];
#pragma unroll
        for (int q = 0; q < 4; q++) {
            float4 a = *(const float4*)&hb[f][vr][vc + 4 * q];
            v[4 * q + 0] = a.x; v[4 * q + 1] = a.y;
            v[4 * q + 2] = a.z; v[4 * q + 3] = a.w;
        }
#pragma unroll
        for (int t = 0; t < 14; t++) {
#pragma unroll
            for (int k = 0; k < 4; k++) {
                int tt = t - k;
                if (tt >= 0 && tt <= 10)
                    m[f][k] += gw(tt) * v[t];
            }
        }
    }

    const float C1 = 4.0e-4f;   // (0.01*2)^2
    const float C2 = 3.6e-3f;   // (0.03*2)^2
    float lsum = 0.f;
#pragma unroll
    for (int k = 0; k < 4; k++) {
        float mu1 = m[0][k], mu2 = m[1][k];
        float x2 = m[2][k], y2 = m[3][k], xy = m[4][k];
        float mu1sq = mu1 * mu1;
        float mu2sq = mu2 * mu2;
        float mu12  = mu1 * mu2;
        float s1c   = x2 - mu1sq;
        float s2c   = y2 - mu2sq;
        float s12   = xy - mu12;
        float num   = (2.f * mu12 + C1) * (2.f * s12 + C2);
        float den   = (mu1sq + mu2sq + C1) * (s1c + s2c + C2);
        lsum += __fdividef(num, den + 1e-8f);
    }

    // ---- block reduction -> one double atomic per block ----
#pragma unroll
    for (int o = 16; o > 0; o >>= 1)
        lsum += __shfl_xor_sync(0xFFFFFFFFu, lsum, o);
    if ((tid & 31) == 0) wsum[tid >> 5] = lsum;
    __syncthreads();
    if (tid == 0) {
        float b = 0.f;
#pragma unroll
        for (int i = 0; i < 8; i++) b += wsum[i];
        atomicAdd(acc, (double)b);
    }
}

__global__ void finish_kernel(float* __restrict__ out) {
    const double w[5] = {0.0448, 0.2856, 0.3001, 0.2363, 0.1333};
    const double wsumv = 1.0001;  // reference normalizes by the weight sum
    double cnt = (double)NIMG * 512.0 * 512.0;
    double m = 0.0;
#pragma unroll
    for (int l = 0; l < 5; l++) {
        m += (w[l] / wsumv) * (g_acc[l] / cnt);
        cnt *= 0.25;
    }
    out[0] = (float)(1.0 - m);
}

extern "C" void kernel_launch(void* const* d_in, const int* in_sizes, int n_in,
                              void* d_out, int out_size)
{
    (void)in_sizes; (void)n_in; (void)out_size;
    const float* pred   = (const float*)d_in[0];
    const float* target = (const float*)d_in[1];
    float* out = (float*)d_out;

    float *bAx, *bAy, *bBx, *bBy;
    double* acc;
    cudaGetSymbolAddress((void**)&bAx, g_bufAx);
    cudaGetSymbolAddress((void**)&bAy, g_bufAy);
    cudaGetSymbolAddress((void**)&bBx, g_bufBx);
    cudaGetSymbolAddress((void**)&bBy, g_bufBy);
    cudaGetSymbolAddress((void**)&acc, g_acc);

    zero_acc_kernel<<<1, 32>>>();

    // L0 512^2 : SSIM + pool -> A (256^2)
    ssim_level_kernel<true ><<<dim3(16, 16, NIMG), 256>>>(pred, target, 512, 512, acc + 0, bAx, bAy);
    // L1 256^2 : SSIM + pool -> B (128^2)
    ssim_level_kernel<true ><<<dim3(8, 8, NIMG), 256>>>(bAx, bAy, 256, 256, acc + 1, bBx, bBy);
    // L2 128^2 : SSIM + pool -> A (64^2, reuse)
    ssim_level_kernel<true ><<<dim3(4, 4, NIMG), 256>>>(bBx, bBy, 128, 128, acc + 2, bAx, bAy);
    // L3 64^2  : SSIM + pool -> B (32^2, reuse)
    ssim_level_kernel<true ><<<dim3(2, 2, NIMG), 256>>>(bAx, bAy, 64, 64, acc + 3, bBx, bBy);
    // L4 32^2  : SSIM only
    ssim_level_kernel<false><<<dim3(1, 1, NIMG), 256>>>(bBx, bBy, 32, 32, acc + 4, nullptr, nullptr);

    finish_kernel<<<1, 1>>>(out);
}